// round 13
// baseline (speedup 1.0000x reference)
#include <cuda_runtime.h>
#include <math.h>

typedef unsigned long long ull;

#define N_BATCH 64
#define L0 16000
#define LP1 5306
#define LP2 1742
#define LP3 554
#define LP4 158
#define LP5 26

// ---------------- scratch (device globals; no allocation allowed) ----------------
__device__ float g_h0[N_BATCH*3*L0];
__device__ float g_p1[N_BATCH*64*LP1];
__device__ ull   g_pk1[N_BATCH*LP1];
__device__ float g_p2[N_BATCH*64*LP2];
__device__ ull   g_pk2[N_BATCH*LP2];
__device__ float g_p3[N_BATCH*64*LP3];
__device__ ull   g_pk3[N_BATCH*LP3];
__device__ float g_p4[N_BATCH*64*LP4];
__device__ ull   g_pk4[N_BATCH*LP4];
__device__ float g_p5[N_BATCH*32*LP5];
__device__ ull   g_pk5[N_BATCH*13];
__device__ float g_fc1o[N_BATCH*1024];
__device__ ull   g_pk6[N_BATCH*16];
__device__ float g_fc2o[N_BATCH*1000];

__device__ float g_sw1[64*3*41];
__device__ ull   g_w2[41*64];
__device__ ull   g_w3[41*64];
__device__ ull   g_w4[41*64];
__device__ ull   g_w5[41*32];
__device__ ull   g_wfc1[1024*13];
__device__ ull   g_wfc2[1000*16];

__device__ double g_sum[64], g_ssq[64];
__device__ float  g_a[1024], g_bb[1024];   // folded scale/shift (integer-grid layers + fc)
__device__ float  g_mf[64],  g_sf[64];     // fp32-mimic mean / sqrt(var+eps) (bn0, bn1)

// ---------------- weight prep ----------------
__global__ void k_signw1(const float* __restrict__ w){
    int idx = blockIdx.x*blockDim.x + threadIdx.x;
    if (idx >= 64*3*41) return;
    float v = w[idx];
    g_sw1[idx] = (v > 0.f) ? 1.f : ((v < 0.f) ? -1.f : 0.f);
}

__global__ void k_packw(const float* __restrict__ w, ull* __restrict__ wp, int COUT){
    int idx = blockIdx.x*blockDim.x + threadIdx.x;
    if (idx >= 41*COUT) return;
    int k = idx / COUT, o = idx - k*COUT;
    ull word = 0;
    #pragma unroll 8
    for (int c = 0; c < 64; c++)
        if (w[(o*64 + c)*41 + k] > 0.f) word |= (1ull << c);
    wp[k*COUT + o] = word;
}

__global__ void k_packw_fc(const float* __restrict__ w, ull* __restrict__ wp, int F, int W){
    int idx = blockIdx.x*blockDim.x + threadIdx.x;
    if (idx >= F*W) return;
    int f = idx / W, wd = idx - f*W;
    int INF = W*64;
    ull word = 0;
    #pragma unroll 8
    for (int j = 0; j < 64; j++)
        if (w[f*INF + wd*64 + j] > 0.f) word |= (1ull << j);
    wp[idx] = word;
}

// ---------------- batchnorm stats ----------------
__global__ void k_zero_stats(int C){
    int i = threadIdx.x;
    if (i < C){ g_sum[i] = 0.0; g_ssq[i] = 0.0; }
}

__global__ void k_stats(const float* __restrict__ p, int C, int L){
    int c = blockIdx.x;
    int NL = N_BATCH * L;
    double s = 0.0, s2 = 0.0;
    for (int idx = blockIdx.y*blockDim.x + threadIdx.x; idx < NL; idx += gridDim.y*blockDim.x){
        int n = idx / L, l = idx - n*L;
        float v = p[(n*C + c)*L + l];
        s += (double)v; s2 += (double)v*(double)v;
    }
    __shared__ double sh[256], sh2[256];
    int t = threadIdx.x;
    sh[t] = s; sh2[t] = s2; __syncthreads();
    for (int st = 128; st > 0; st >>= 1){
        if (t < st){ sh[t] += sh[t+st]; sh2[t] += sh2[t+st]; }
        __syncthreads();
    }
    if (t == 0){ atomicAdd(&g_sum[c], sh[0]); atomicAdd(&g_ssq[c], sh2[0]); }
}

// folded a/bb (for integer-grid layers) AND fp32-mimic m/s (for continuous layers)
__global__ void k_finalize(const float* __restrict__ g, const float* __restrict__ b, int C, double cnt){
    int c = blockIdx.x*blockDim.x + threadIdx.x;
    if (c >= C) return;
    double m = g_sum[c]/cnt;
    double v = g_ssq[c]/cnt - m*m;
    double a = (double)g[c] / sqrt(v + 1e-5);
    g_a[c]  = (float)a;
    g_bb[c] = (float)((double)b[c] - m*a);
    float vf = (float)v;
    g_mf[c] = (float)m;
    g_sf[c] = __fsqrt_rn(__fadd_rn(vf, 1e-5f));   // fp32: sqrt(var + eps)
}

// ---------------- layer 0: bn0 + hardtanh — IEEE fp32 mimic of ((x-m)/s)*g+b ----
__global__ void k_apply_h0(const float* __restrict__ x, const float* __restrict__ g,
                           const float* __restrict__ b){
    int idx = blockIdx.x*blockDim.x + threadIdx.x;
    if (idx >= N_BATCH*3*L0) return;
    int c = (idx / L0) % 3;
    float t1 = __fadd_rn(x[idx], -g_mf[c]);
    float t2 = __fdiv_rn(t1, g_sf[c]);
    float t3 = __fmul_rn(t2, g[c]);
    float t4 = __fadd_rn(t3, b[c]);
    g_h0[idx] = fminf(1.f, fmaxf(-1.f, t4));
}

// ---------------- conv1: Kahan-compensated fp32, bias + maxpool3 fused ----------
// 512 threads = 64 out-channels x 8 groups; each thread: 4 pooled (12 raw) outputs.
__global__ void __launch_bounds__(512) k_conv1(const float* __restrict__ bias){
    __shared__ float s_in[3][184];                 // 96 raw + 80 halo (176 used)
    __shared__ float s_w[3*41*64];                 // [c*41+k][o]
    int n  = blockIdx.x;
    int pb = blockIdx.y * 32;
    int rawbase = pb*3;
    int tid = threadIdx.x;
    int o = tid & 63, grp = tid >> 6;              // grp 0..7
    for (int i = tid; i < 3*176; i += 512){
        int c = i / 176, j = i - c*176;
        int src = rawbase + j; if (src > L0-1) src = L0-1;
        s_in[c][j] = g_h0[(n*3+c)*L0 + src];
    }
    for (int i = tid; i < 64*3*41; i += 512){
        int oo = i / 123, r = i - oo*123;
        s_w[r*64 + oo] = g_sw1[i];
    }
    __syncthreads();
    float acc[12], cmp[12];
    #pragma unroll
    for (int r = 0; r < 12; r++){ acc[r] = 0.f; cmp[r] = 0.f; }
    int tb = grp*12;                               // even -> float2 aligned
    #pragma unroll 1
    for (int c = 0; c < 3; c++){
        #pragma unroll 1
        for (int k = 0; k < 41; k++){
            float w = s_w[(c*41+k)*64 + o];
            const float2* ip = (const float2*)&s_in[c][tb + 2*k];
            #pragma unroll
            for (int r = 0; r < 6; r++){
                float2 u = ip[r];
                {   // Kahan on acc[2r]
                    float p = __fmul_rn(w, u.x);
                    float y = __fadd_rn(p, -cmp[2*r]);
                    float t = __fadd_rn(acc[2*r], y);
                    cmp[2*r] = __fadd_rn(__fadd_rn(t, -acc[2*r]), -y);
                    acc[2*r] = t;
                }
                {   // Kahan on acc[2r+1]
                    float p = __fmul_rn(w, u.y);
                    float y = __fadd_rn(p, -cmp[2*r+1]);
                    float t = __fadd_rn(acc[2*r+1], y);
                    cmp[2*r+1] = __fadd_rn(__fadd_rn(t, -acc[2*r+1]), -y);
                    acc[2*r+1] = t;
                }
            }
        }
    }
    float b = bias[o];
    #pragma unroll
    for (int gq = 0; gq < 4; gq++){
        int p = pb + grp*4 + gq;
        if (p < LP1){
            float m = fmaxf(acc[gq*3], fmaxf(acc[gq*3+1], acc[gq*3+2]));
            g_p1[(n*64+o)*LP1 + p] = __fadd_rn(m, b);
        }
    }
}

// ---------------- bn1 sign-pack: IEEE fp32 mimic of ((v-m)/s)*g+b > 0 -----------
__global__ void k_bnpack1(const float* __restrict__ p, ull* __restrict__ pk, int L,
                          const float* __restrict__ g, const float* __restrict__ b){
    int idx = blockIdx.x*blockDim.x + threadIdx.x;
    if (idx >= N_BATCH*L) return;
    int n = idx / L, l = idx - n*L;
    ull w = 0;
    #pragma unroll 8
    for (int c = 0; c < 64; c++){
        float t1 = __fadd_rn(p[(n*64+c)*L + l], -g_mf[c]);
        float t2 = __fdiv_rn(t1, g_sf[c]);
        float t3 = __fmul_rn(t2, g[c]);
        float t4 = __fadd_rn(t3, b[c]);
        if (t4 > 0.f) w |= (1ull << c);
    }
    pk[idx] = w;
}

// ---------------- sign-pack via folded BN (safe on integer-grid layers) ---------
__global__ void k_bnpack(const float* __restrict__ p, ull* __restrict__ pk, int L){
    int idx = blockIdx.x*blockDim.x + threadIdx.x;
    if (idx >= N_BATCH*L) return;
    int n = idx / L, l = idx - n*L;
    ull w = 0;
    #pragma unroll 8
    for (int c = 0; c < 64; c++){
        float v = p[(n*64+c)*L + l]*g_a[c] + g_bb[c];
        if (v > 0.f) w |= (1ull << c);
    }
    pk[idx] = w;
}

// ---------------- binarized conv (Cin=64) + bias + maxpool3 ---------------------
template<int COUT, int GRPS, int G>
__global__ void __launch_bounds__(COUT*GRPS)
k_binconv(const ull* __restrict__ in, const ull* __restrict__ wp,
          const float* __restrict__ bias, float* __restrict__ out,
          int Lin, int Lpool){
    const int PB = GRPS*G;
    const int TI = 3*PB + 80;
    __shared__ __align__(16) ull s_in[TI];
    __shared__ ull s_w[41*COUT];
    int n  = blockIdx.x;
    int pb = blockIdx.y*PB;
    int rawbase = 3*pb;
    int tid = threadIdx.x;
    int o = tid % COUT, grp = tid / COUT;
    for (int i = tid; i < TI; i += COUT*GRPS){
        int src = rawbase + i; if (src > Lin-1) src = Lin-1;
        s_in[i] = in[n*Lin + src];
    }
    for (int i = tid; i < 41*COUT; i += COUT*GRPS) s_w[i] = wp[i];
    __syncthreads();
    int acc[3*G];
    #pragma unroll
    for (int r = 0; r < 3*G; r++) acc[r] = 0;
    int tb = grp*3*G;
    #pragma unroll 1
    for (int k = 0; k < 41; k++){
        ull wv = s_w[k*COUT + o];
        const ulonglong2* ip = (const ulonglong2*)&s_in[tb + 2*k];
        #pragma unroll
        for (int r = 0; r < (3*G)/2; r++){
            ulonglong2 u = ip[r];
            acc[2*r]   += __popcll(u.x ^ wv);
            acc[2*r+1] += __popcll(u.y ^ wv);
        }
    }
    float b = bias[o];
    #pragma unroll
    for (int gq = 0; gq < G; gq++){
        int p = pb + grp*G + gq;
        if (p < Lpool){
            int v0 = 2624 - 2*acc[gq*3];
            int v1 = 2624 - 2*acc[gq*3+1];
            int v2 = 2624 - 2*acc[gq*3+2];
            int m = max(v0, max(v1, v2));
            out[(n*COUT+o)*Lpool + p] = __fadd_rn((float)m, b);
        }
    }
}

// ---------------- fc path ----------------
__global__ void k_packfc1in(){
    int idx = blockIdx.x*blockDim.x + threadIdx.x;
    if (idx >= N_BATCH*13) return;
    int n = idx / 13, wd = idx - n*13;
    ull word = 0;
    #pragma unroll 8
    for (int j = 0; j < 64; j++){
        float v = g_p5[n*832 + wd*64 + j];
        if (v > 0.f) word |= (1ull << j);
    }
    g_pk5[idx] = word;
}

__global__ void k_fc(const ull* __restrict__ inpk, const ull* __restrict__ wpk,
                     const float* __restrict__ bias, float* __restrict__ out,
                     int F, int W, int INB){
    int idx = blockIdx.x*blockDim.x + threadIdx.x;
    if (idx >= N_BATCH*F) return;
    int n = idx / F, f = idx - n*F;
    int acc = 0;
    for (int w = 0; w < W; w++) acc += __popcll(inpk[n*W+w] ^ wpk[f*W+w]);
    out[idx] = __fadd_rn((float)(INB - 2*acc), bias[f]);
}

__global__ void k_bnfc(const float* __restrict__ o, const float* __restrict__ g,
                       const float* __restrict__ b, int F){
    int f = blockIdx.x*blockDim.x + threadIdx.x;
    if (f >= F) return;
    double s = 0.0, s2 = 0.0;
    for (int n = 0; n < N_BATCH; n++){
        float v = o[n*F + f];
        s += (double)v; s2 += (double)v*(double)v;
    }
    double m = s / N_BATCH, var = s2 / N_BATCH - m*m;
    double a = (double)g[f] / sqrt(var + 1e-5);
    g_a[f]  = (float)a;
    g_bb[f] = (float)((double)b[f] - m*a);
}

__global__ void k_pack6(){
    int idx = blockIdx.x*blockDim.x + threadIdx.x;
    if (idx >= N_BATCH*16) return;
    int n = idx / 16, wd = idx - n*16;
    ull word = 0;
    #pragma unroll 8
    for (int j = 0; j < 64; j++){
        int f = wd*64 + j;
        float v = g_fc1o[n*1024+f]*g_a[f] + g_bb[f];
        if (v > 0.f) word |= (1ull << j);
    }
    g_pk6[idx] = word;
}

__global__ void k_logsoftmax(float* __restrict__ out){
    int n = blockIdx.x;
    int t = threadIdx.x;
    float yv[4];
    float mx = -1e30f;
    #pragma unroll
    for (int s = 0; s < 4; s++){
        int f = t + s*256;
        if (f < 1000){
            float y = g_fc2o[n*1000+f]*g_a[f] + g_bb[f];
            yv[s] = y; mx = fmaxf(mx, y);
        } else yv[s] = -1e30f;
    }
    __shared__ float sh[256];
    sh[t] = mx; __syncthreads();
    for (int st = 128; st > 0; st >>= 1){
        if (t < st) sh[t] = fmaxf(sh[t], sh[t+st]);
        __syncthreads();
    }
    mx = sh[0]; __syncthreads();
    float se = 0.f;
    #pragma unroll
    for (int s = 0; s < 4; s++){
        int f = t + s*256;
        if (f < 1000) se += expf(yv[s] - mx);
    }
    sh[t] = se; __syncthreads();
    for (int st = 128; st > 0; st >>= 1){
        if (t < st) sh[t] += sh[t+st];
        __syncthreads();
    }
    float lse = logf(sh[0]);
    #pragma unroll
    for (int s = 0; s < 4; s++){
        int f = t + s*256;
        if (f < 1000) out[n*1000+f] = yv[s] - mx - lse;
    }
}

// ---------------- launch ----------------
extern "C" void kernel_launch(void* const* d_in, const int* in_sizes, int n_in,
                              void* d_out, int out_size){
    const float* x       = (const float*)d_in[0];
    const float* bn0_g   = (const float*)d_in[1];
    const float* bn0_b   = (const float*)d_in[2];
    const float* conv1_w = (const float*)d_in[3];
    const float* conv1_b = (const float*)d_in[4];
    const float* bn1_g   = (const float*)d_in[5];
    const float* bn1_b   = (const float*)d_in[6];
    const float* conv2_w = (const float*)d_in[7];
    const float* conv2_b = (const float*)d_in[8];
    const float* bn2_g   = (const float*)d_in[9];
    const float* bn2_b   = (const float*)d_in[10];
    const float* conv3_w = (const float*)d_in[11];
    const float* conv3_b = (const float*)d_in[12];
    const float* bn3_g   = (const float*)d_in[13];
    const float* bn3_b   = (const float*)d_in[14];
    const float* conv4_w = (const float*)d_in[15];
    const float* conv4_b = (const float*)d_in[16];
    const float* bn4_g   = (const float*)d_in[17];
    const float* bn4_b   = (const float*)d_in[18];
    const float* conv5_w = (const float*)d_in[19];
    const float* conv5_b = (const float*)d_in[20];
    const float* fc1_w   = (const float*)d_in[21];
    const float* fc1_b   = (const float*)d_in[22];
    const float* bn5_g   = (const float*)d_in[23];
    const float* bn5_b   = (const float*)d_in[24];
    const float* fc2_w   = (const float*)d_in[25];
    const float* fc2_b   = (const float*)d_in[26];
    const float* bn6_g   = (const float*)d_in[27];
    const float* bn6_b   = (const float*)d_in[28];
    float* out = (float*)d_out;

    float *p1, *p2, *p3, *p4, *fc1o, *fc2o;
    ull *pk1, *pk2, *pk3, *pk4, *pk5, *pk6, *w2, *w3, *w4, *w5, *wfc1, *wfc2;
    cudaGetSymbolAddress((void**)&p1,   g_p1);
    cudaGetSymbolAddress((void**)&p2,   g_p2);
    cudaGetSymbolAddress((void**)&p3,   g_p3);
    cudaGetSymbolAddress((void**)&p4,   g_p4);
    cudaGetSymbolAddress((void**)&fc1o, g_fc1o);
    cudaGetSymbolAddress((void**)&fc2o, g_fc2o);
    cudaGetSymbolAddress((void**)&pk1,  g_pk1);
    cudaGetSymbolAddress((void**)&pk2,  g_pk2);
    cudaGetSymbolAddress((void**)&pk3,  g_pk3);
    cudaGetSymbolAddress((void**)&pk4,  g_pk4);
    cudaGetSymbolAddress((void**)&pk5,  g_pk5);
    cudaGetSymbolAddress((void**)&pk6,  g_pk6);
    cudaGetSymbolAddress((void**)&w2,   g_w2);
    cudaGetSymbolAddress((void**)&w3,   g_w3);
    cudaGetSymbolAddress((void**)&w4,   g_w4);
    cudaGetSymbolAddress((void**)&w5,   g_w5);
    cudaGetSymbolAddress((void**)&wfc1, g_wfc1);
    cudaGetSymbolAddress((void**)&wfc2, g_wfc2);

    float *p5;
    cudaGetSymbolAddress((void**)&p5, g_p5);

    // weight prep
    k_signw1 <<<(64*3*41 + 255)/256, 256>>>(conv1_w);
    k_packw  <<<(41*64   + 255)/256, 256>>>(conv2_w, w2, 64);
    k_packw  <<<(41*64   + 255)/256, 256>>>(conv3_w, w3, 64);
    k_packw  <<<(41*64   + 255)/256, 256>>>(conv4_w, w4, 64);
    k_packw  <<<(41*32   + 255)/256, 256>>>(conv5_w, w5, 32);
    k_packw_fc<<<(1024*13 + 255)/256, 256>>>(fc1_w, wfc1, 1024, 13);
    k_packw_fc<<<(1000*16 + 255)/256, 256>>>(fc2_w, wfc2, 1000, 16);

    // bn0 + hardtanh (fp32 mimic)
    k_zero_stats<<<1, 64>>>(3);
    k_stats   <<<dim3(3, 32), 256>>>(x, 3, L0);
    k_finalize<<<1, 64>>>(bn0_g, bn0_b, 3, (double)N_BATCH*(double)L0);
    k_apply_h0<<<(N_BATCH*3*L0 + 255)/256, 256>>>(x, bn0_g, bn0_b);

    // conv1 (Kahan) + bias + pool
    k_conv1<<<dim3(N_BATCH, (LP1 + 31)/32), 512>>>(conv1_b);

    // bn1 + sign-pack (fp32 mimic)
    k_zero_stats<<<1, 64>>>(64);
    k_stats   <<<dim3(64, 16), 256>>>(p1, 64, LP1);
    k_finalize<<<1, 64>>>(bn1_g, bn1_b, 64, (double)N_BATCH*(double)LP1);
    k_bnpack1 <<<(N_BATCH*LP1 + 255)/256, 256>>>(p1, pk1, LP1, bn1_g, bn1_b);

    // conv2
    k_binconv<64,4,4><<<dim3(N_BATCH, (LP2 + 15)/16), 256>>>(pk1, w2, conv2_b, p2, LP1, LP2);
    k_zero_stats<<<1, 64>>>(64);
    k_stats   <<<dim3(64, 16), 256>>>(p2, 64, LP2);
    k_finalize<<<1, 64>>>(bn2_g, bn2_b, 64, (double)N_BATCH*(double)LP2);
    k_bnpack  <<<(N_BATCH*LP2 + 255)/256, 256>>>(p2, pk2, LP2);

    // conv3
    k_binconv<64,4,4><<<dim3(N_BATCH, (LP3 + 15)/16), 256>>>(pk2, w3, conv3_b, p3, LP2, LP3);
    k_zero_stats<<<1, 64>>>(64);
    k_stats   <<<dim3(64, 16), 256>>>(p3, 64, LP3);
    k_finalize<<<1, 64>>>(bn3_g, bn3_b, 64, (double)N_BATCH*(double)LP3);
    k_bnpack  <<<(N_BATCH*LP3 + 255)/256, 256>>>(p3, pk3, LP3);

    // conv4
    k_binconv<64,4,4><<<dim3(N_BATCH, (LP4 + 15)/16), 256>>>(pk3, w4, conv4_b, p4, LP3, LP4);
    k_zero_stats<<<1, 64>>>(64);
    k_stats   <<<dim3(64, 16), 256>>>(p4, 64, LP4);
    k_finalize<<<1, 64>>>(bn4_g, bn4_b, 64, (double)N_BATCH*(double)LP4);
    k_bnpack  <<<(N_BATCH*LP4 + 255)/256, 256>>>(p4, pk4, LP4);

    // conv5 + fc path
    k_binconv<32,8,2><<<dim3(N_BATCH, (LP5 + 15)/16), 256>>>(pk4, w5, conv5_b, p5, LP4, LP5);
    k_packfc1in<<<(N_BATCH*13 + 255)/256, 256>>>();

    k_fc   <<<(N_BATCH*1024 + 255)/256, 256>>>(pk5, wfc1, fc1_b, fc1o, 1024, 13, 832);
    k_bnfc <<<(1024 + 255)/256, 256>>>(fc1o, bn5_g, bn5_b, 1024);
    k_pack6<<<(N_BATCH*16 + 255)/256, 256>>>();

    k_fc   <<<(N_BATCH*1000 + 255)/256, 256>>>(pk6, wfc2, fc2_b, fc2o, 1000, 16, 1024);
    k_bnfc <<<(1000 + 255)/256, 256>>>(fc2o, bn6_g, bn6_b, 1000);
    k_logsoftmax<<<N_BATCH, 256>>>(out);
}

// round 15
// speedup vs baseline: 1.2584x; 1.2584x over previous
#include <cuda_runtime.h>
#include <math.h>

typedef unsigned long long ull;
typedef signed char schar;   // 'char' is UNSIGNED on aarch64 — must be explicit

#define N_BATCH 64
#define L0 16000
#define LP1 5306
#define LP2 1742
#define LP3 554
#define LP4 158
#define LP5 26

// ---------------- scratch (device globals; no allocation allowed) ----------------
__device__ int   g_h0i[N_BATCH*3*L0];       // round(h * 2^20), exact int part
__device__ float g_h0r[N_BATCH*3*L0];       // h - i*2^-20, exact residual
__device__ float g_p1[N_BATCH*64*LP1];
__device__ ull   g_pk1[N_BATCH*LP1];
__device__ float g_p2[N_BATCH*64*LP2];
__device__ ull   g_pk2[N_BATCH*LP2];
__device__ float g_p3[N_BATCH*64*LP3];
__device__ ull   g_pk3[N_BATCH*LP3];
__device__ float g_p4[N_BATCH*64*LP4];
__device__ ull   g_pk4[N_BATCH*LP4];
__device__ float g_p5[N_BATCH*32*LP5];
__device__ ull   g_pk5[N_BATCH*13];
__device__ float g_fc1o[N_BATCH*1024];
__device__ ull   g_pk6[N_BATCH*16];
__device__ float g_fc2o[N_BATCH*1000];

__device__ schar g_w1code[123*64];          // conv1 weight sign codes, [(c*41+k)*64+o]
__device__ ull   g_w2[41*64];
__device__ ull   g_w3[41*64];
__device__ ull   g_w4[41*64];
__device__ ull   g_w5[41*32];
__device__ ull   g_wfc1[1024*13];
__device__ ull   g_wfc2[1000*16];

__device__ double g_sum[64], g_ssq[64];
__device__ float  g_a[1024], g_bb[1024];    // folded scale/shift (integer-grid layers + fc)
__device__ float  g_mf[64],  g_sf[64];      // fp32-mimic mean / sqrt(var+eps) (bn0, bn1)

// ---------------- weight prep ----------------
__global__ void k_codew1(const float* __restrict__ w){
    int idx = blockIdx.x*blockDim.x + threadIdx.x;   // idx = o*123 + (c*41+k)
    if (idx >= 64*123) return;
    int o = idx / 123, r = idx - o*123;
    float v = w[idx];
    schar code = (v > 0.f) ? (schar)1 : ((v < 0.f) ? (schar)-1 : (schar)0);
    g_w1code[r*64 + o] = code;
}

__global__ void k_packw(const float* __restrict__ w, ull* __restrict__ wp, int COUT){
    int idx = blockIdx.x*blockDim.x + threadIdx.x;
    if (idx >= 41*COUT) return;
    int k = idx / COUT, o = idx - k*COUT;
    ull word = 0;
    #pragma unroll 8
    for (int c = 0; c < 64; c++)
        if (w[(o*64 + c)*41 + k] > 0.f) word |= (1ull << c);
    wp[k*COUT + o] = word;
}

__global__ void k_packw_fc(const float* __restrict__ w, ull* __restrict__ wp, int F, int W){
    int idx = blockIdx.x*blockDim.x + threadIdx.x;
    if (idx >= F*W) return;
    int f = idx / W, wd = idx - f*W;
    int INF = W*64;
    ull word = 0;
    #pragma unroll 8
    for (int j = 0; j < 64; j++)
        if (w[f*INF + wd*64 + j] > 0.f) word |= (1ull << j);
    wp[idx] = word;
}

// ---------------- batchnorm stats ----------------
__global__ void k_zero_stats(int C){
    int i = threadIdx.x;
    if (i < C){ g_sum[i] = 0.0; g_ssq[i] = 0.0; }
}

__global__ void k_stats(const float* __restrict__ p, int C, int L){
    int c = blockIdx.x;
    int NL = N_BATCH * L;
    double s = 0.0, s2 = 0.0;
    for (int idx = blockIdx.y*blockDim.x + threadIdx.x; idx < NL; idx += gridDim.y*blockDim.x){
        int n = idx / L, l = idx - n*L;
        float v = p[(n*C + c)*L + l];
        s += (double)v; s2 += (double)v*(double)v;
    }
    __shared__ double sh[256], sh2[256];
    int t = threadIdx.x;
    sh[t] = s; sh2[t] = s2; __syncthreads();
    for (int st = 128; st > 0; st >>= 1){
        if (t < st){ sh[t] += sh[t+st]; sh2[t] += sh2[t+st]; }
        __syncthreads();
    }
    if (t == 0){ atomicAdd(&g_sum[c], sh[0]); atomicAdd(&g_ssq[c], sh2[0]); }
}

__global__ void k_finalize(const float* __restrict__ g, const float* __restrict__ b, int C, double cnt){
    int c = blockIdx.x*blockDim.x + threadIdx.x;
    if (c >= C) return;
    double m = g_sum[c]/cnt;
    double v = g_ssq[c]/cnt - m*m;
    double a = (double)g[c] / sqrt(v + 1e-5);
    g_a[c]  = (float)a;
    g_bb[c] = (float)((double)b[c] - m*a);
    float vf = (float)v;
    g_mf[c] = (float)m;
    g_sf[c] = __fsqrt_rn(__fadd_rn(vf, 1e-5f));
}

// ---------------- layer 0: bn0 + hardtanh (fp32 mimic) + exact int/residual split
__global__ void k_apply_h0(const float* __restrict__ x, const float* __restrict__ g,
                           const float* __restrict__ b){
    int idx = blockIdx.x*blockDim.x + threadIdx.x;
    if (idx >= N_BATCH*3*L0) return;
    int c = (idx / L0) % 3;
    float t1 = __fadd_rn(x[idx], -g_mf[c]);
    float t2 = __fdiv_rn(t1, g_sf[c]);
    float t3 = __fmul_rn(t2, g[c]);
    float t4 = __fadd_rn(t3, b[c]);
    float h  = fminf(1.f, fmaxf(-1.f, t4));
    float t  = __fmul_rn(h, 1048576.0f);          // h * 2^20, exact (pow2)
    int   i  = __float2int_rn(t);
    float fi = (float)i;                           // |i| <= 2^20 -> exact
    float r  = __fmaf_rn(fi, -0x1p-20f, h);        // exact residual
    g_h0i[idx] = i;
    g_h0r[idx] = r;
}

// ---------------- conv1: exact integer-split conv (3->64, K=41, dil=2) + bias + maxpool3
// 512 threads = 64 out-channels x 8 groups; each thread: 4 pooled (12 raw) outputs.
// sum = (int32 exact part)*2^-20 + fp32 residual part; recombined to <=1 ulp of exact.
__global__ void __launch_bounds__(512) k_conv1(const float* __restrict__ bias){
    __shared__ int   s_ii[3][192];
    __shared__ float s_ir[3][192];
    __shared__ schar s_code[123*64];
    int n  = blockIdx.x;
    int pb = blockIdx.y * 32;                      // pooled base
    int rawbase = pb*3;
    int tid = threadIdx.x;
    int o = tid & 63, grp = tid >> 6;              // grp 0..7
    for (int i = tid; i < 3*192; i += 512){
        int c = i / 192, j = i - c*192;
        int src = rawbase + j; if (src > L0-1) src = L0-1;
        s_ii[c][j] = g_h0i[(n*3+c)*L0 + src];
        s_ir[c][j] = g_h0r[(n*3+c)*L0 + src];
    }
    for (int i = tid; i < 123*64; i += 512) s_code[i] = g_w1code[i];
    __syncthreads();

    float accr[12]; int acci[12];
    #pragma unroll
    for (int r = 0; r < 12; r++){ accr[r] = 0.f; acci[r] = 0; }
    int tb = grp*12;                               // even -> 8B-aligned pair loads

    #pragma unroll 1
    for (int c = 0; c < 3; c++){
        int   iwin[12]; float rwin[12];
        #pragma unroll
        for (int r = 0; r < 12; r++){ iwin[r] = s_ii[c][tb+r]; rwin[r] = s_ir[c][tb+r]; }
        #pragma unroll
        for (int k = 0; k < 41; k++){
            int wi = (int)s_code[(c*41+k)*64 + o];     // -1 / 0 / +1 (signed!)
            float wf = (float)wi;
            int X  = wi >> 31;                          // -1 if neg else 0
            int A  = (wi | (-wi)) >> 31;                // -1 if nonzero else 0
            int cb = ((unsigned)wi) >> 31;              // +1 if neg else 0
            #pragma unroll
            for (int r = 0; r < 12; r++)
                accr[r] = __fmaf_rn(wf, rwin[r], accr[r]);
            #pragma unroll
            for (int r = 0; r < 6; r++)                 // fma-pipe int MAC
                acci[r] += wi * iwin[r];
            #pragma unroll
            for (int r = 6; r < 12; r++)                // alu-pipe: LOP3 + IADD3
                acci[r] = acci[r] + (((iwin[r] & A) ^ X)) + cb;
            if (k < 40){
                #pragma unroll
                for (int r = 0; r < 10; r++){ iwin[r] = iwin[r+2]; rwin[r] = rwin[r+2]; }
                int2   iv = *(const int2*  )&s_ii[c][tb + 2*k + 12];
                float2 fv = *(const float2*)&s_ir[c][tb + 2*k + 12];
                iwin[10] = iv.x; iwin[11] = iv.y;
                rwin[10] = fv.x; rwin[11] = fv.y;
            }
        }
    }

    const float S = 0x1p-20f;
    float b = bias[o];
    #pragma unroll
    for (int gq = 0; gq < 4; gq++){
        int p = pb + grp*4 + gq;
        if (p < LP1){
            float v[3];
            #pragma unroll
            for (int q = 0; q < 3; q++){
                int ai = acci[gq*3+q];
                int lo = ai & 4095;
                int hi2 = ai - lo;                      // multiple of 4096, exact in fp32
                float fint = __fadd_rn(__fmul_rn((float)hi2, S), __fmul_rn((float)lo, S));
                v[q] = __fadd_rn(fint, accr[gq*3+q]);
            }
            float m = fmaxf(v[0], fmaxf(v[1], v[2]));
            g_p1[(n*64+o)*LP1 + p] = __fadd_rn(m, b);
        }
    }
}

// ---------------- bn1 sign-pack: IEEE fp32 mimic of ((v-m)/s)*g+b > 0 -----------
__global__ void k_bnpack1(const float* __restrict__ p, ull* __restrict__ pk, int L,
                          const float* __restrict__ g, const float* __restrict__ b){
    int idx = blockIdx.x*blockDim.x + threadIdx.x;
    if (idx >= N_BATCH*L) return;
    int n = idx / L, l = idx - n*L;
    ull w = 0;
    #pragma unroll 8
    for (int c = 0; c < 64; c++){
        float t1 = __fadd_rn(p[(n*64+c)*L + l], -g_mf[c]);
        float t2 = __fdiv_rn(t1, g_sf[c]);
        float t3 = __fmul_rn(t2, g[c]);
        float t4 = __fadd_rn(t3, b[c]);
        if (t4 > 0.f) w |= (1ull << c);
    }
    pk[idx] = w;
}

// ---------------- sign-pack via folded BN (safe on integer-grid layers) ---------
__global__ void k_bnpack(const float* __restrict__ p, ull* __restrict__ pk, int L){
    int idx = blockIdx.x*blockDim.x + threadIdx.x;
    if (idx >= N_BATCH*L) return;
    int n = idx / L, l = idx - n*L;
    ull w = 0;
    #pragma unroll 8
    for (int c = 0; c < 64; c++){
        float v = p[(n*64+c)*L + l]*g_a[c] + g_bb[c];
        if (v > 0.f) w |= (1ull << c);
    }
    pk[idx] = w;
}

// ---------------- binarized conv (Cin=64) + bias + maxpool3 ---------------------
template<int COUT, int GRPS, int G>
__global__ void __launch_bounds__(COUT*GRPS)
k_binconv(const ull* __restrict__ in, const ull* __restrict__ wp,
          const float* __restrict__ bias, float* __restrict__ out,
          int Lin, int Lpool){
    const int PB = GRPS*G;
    const int TI = 3*PB + 80;
    __shared__ __align__(16) ull s_in[TI];
    __shared__ ull s_w[41*COUT];
    int n  = blockIdx.x;
    int pb = blockIdx.y*PB;
    int rawbase = 3*pb;
    int tid = threadIdx.x;
    int o = tid % COUT, grp = tid / COUT;
    for (int i = tid; i < TI; i += COUT*GRPS){
        int src = rawbase + i; if (src > Lin-1) src = Lin-1;
        s_in[i] = in[n*Lin + src];
    }
    for (int i = tid; i < 41*COUT; i += COUT*GRPS) s_w[i] = wp[i];
    __syncthreads();
    int acc[3*G];
    #pragma unroll
    for (int r = 0; r < 3*G; r++) acc[r] = 0;
    int tb = grp*3*G;
    #pragma unroll 1
    for (int k = 0; k < 41; k++){
        ull wv = s_w[k*COUT + o];
        const ulonglong2* ip = (const ulonglong2*)&s_in[tb + 2*k];
        #pragma unroll
        for (int r = 0; r < (3*G)/2; r++){
            ulonglong2 u = ip[r];
            acc[2*r]   += __popcll(u.x ^ wv);
            acc[2*r+1] += __popcll(u.y ^ wv);
        }
    }
    float b = bias[o];
    #pragma unroll
    for (int gq = 0; gq < G; gq++){
        int p = pb + grp*G + gq;
        if (p < Lpool){
            int v0 = 2624 - 2*acc[gq*3];
            int v1 = 2624 - 2*acc[gq*3+1];
            int v2 = 2624 - 2*acc[gq*3+2];
            int m = max(v0, max(v1, v2));
            out[(n*COUT+o)*Lpool + p] = __fadd_rn((float)m, b);
        }
    }
}

// ---------------- fc path ----------------
__global__ void k_packfc1in(){
    int idx = blockIdx.x*blockDim.x + threadIdx.x;
    if (idx >= N_BATCH*13) return;
    int n = idx / 13, wd = idx - n*13;
    ull word = 0;
    #pragma unroll 8
    for (int j = 0; j < 64; j++){
        float v = g_p5[n*832 + wd*64 + j];
        if (v > 0.f) word |= (1ull << j);
    }
    g_pk5[idx] = word;
}

__global__ void k_fc(const ull* __restrict__ inpk, const ull* __restrict__ wpk,
                     const float* __restrict__ bias, float* __restrict__ out,
                     int F, int W, int INB){
    int idx = blockIdx.x*blockDim.x + threadIdx.x;
    if (idx >= N_BATCH*F) return;
    int n = idx / F, f = idx - n*F;
    int acc = 0;
    for (int w = 0; w < W; w++) acc += __popcll(inpk[n*W+w] ^ wpk[f*W+w]);
    out[idx] = __fadd_rn((float)(INB - 2*acc), bias[f]);
}

__global__ void k_bnfc(const float* __restrict__ o, const float* __restrict__ g,
                       const float* __restrict__ b, int F){
    int f = blockIdx.x*blockDim.x + threadIdx.x;
    if (f >= F) return;
    double s = 0.0, s2 = 0.0;
    for (int n = 0; n < N_BATCH; n++){
        float v = o[n*F + f];
        s += (double)v; s2 += (double)v*(double)v;
    }
    double m = s / N_BATCH, var = s2 / N_BATCH - m*m;
    double a = (double)g[f] / sqrt(var + 1e-5);
    g_a[f]  = (float)a;
    g_bb[f] = (float)((double)b[f] - m*a);
}

__global__ void k_pack6(){
    int idx = blockIdx.x*blockDim.x + threadIdx.x;
    if (idx >= N_BATCH*16) return;
    int n = idx / 16, wd = idx - n*16;
    ull word = 0;
    #pragma unroll 8
    for (int j = 0; j < 64; j++){
        int f = wd*64 + j;
        float v = g_fc1o[n*1024+f]*g_a[f] + g_bb[f];
        if (v > 0.f) word |= (1ull << j);
    }
    g_pk6[idx] = word;
}

__global__ void k_logsoftmax(float* __restrict__ out){
    int n = blockIdx.x;
    int t = threadIdx.x;
    float yv[4];
    float mx = -1e30f;
    #pragma unroll
    for (int s = 0; s < 4; s++){
        int f = t + s*256;
        if (f < 1000){
            float y = g_fc2o[n*1000+f]*g_a[f] + g_bb[f];
            yv[s] = y; mx = fmaxf(mx, y);
        } else yv[s] = -1e30f;
    }
    __shared__ float sh[256];
    sh[t] = mx; __syncthreads();
    for (int st = 128; st > 0; st >>= 1){
        if (t < st) sh[t] = fmaxf(sh[t], sh[t+st]);
        __syncthreads();
    }
    mx = sh[0]; __syncthreads();
    float se = 0.f;
    #pragma unroll
    for (int s = 0; s < 4; s++){
        int f = t + s*256;
        if (f < 1000) se += expf(yv[s] - mx);
    }
    sh[t] = se; __syncthreads();
    for (int st = 128; st > 0; st >>= 1){
        if (t < st) sh[t] += sh[t+st];
        __syncthreads();
    }
    float lse = logf(sh[0]);
    #pragma unroll
    for (int s = 0; s < 4; s++){
        int f = t + s*256;
        if (f < 1000) out[n*1000+f] = yv[s] - mx - lse;
    }
}

// ---------------- launch ----------------
extern "C" void kernel_launch(void* const* d_in, const int* in_sizes, int n_in,
                              void* d_out, int out_size){
    const float* x       = (const float*)d_in[0];
    const float* bn0_g   = (const float*)d_in[1];
    const float* bn0_b   = (const float*)d_in[2];
    const float* conv1_w = (const float*)d_in[3];
    const float* conv1_b = (const float*)d_in[4];
    const float* bn1_g   = (const float*)d_in[5];
    const float* bn1_b   = (const float*)d_in[6];
    const float* conv2_w = (const float*)d_in[7];
    const float* conv2_b = (const float*)d_in[8];
    const float* bn2_g   = (const float*)d_in[9];
    const float* bn2_b   = (const float*)d_in[10];
    const float* conv3_w = (const float*)d_in[11];
    const float* conv3_b = (const float*)d_in[12];
    const float* bn3_g   = (const float*)d_in[13];
    const float* bn3_b   = (const float*)d_in[14];
    const float* conv4_w = (const float*)d_in[15];
    const float* conv4_b = (const float*)d_in[16];
    const float* bn4_g   = (const float*)d_in[17];
    const float* bn4_b   = (const float*)d_in[18];
    const float* conv5_w = (const float*)d_in[19];
    const float* conv5_b = (const float*)d_in[20];
    const float* fc1_w   = (const float*)d_in[21];
    const float* fc1_b   = (const float*)d_in[22];
    const float* bn5_g   = (const float*)d_in[23];
    const float* bn5_b   = (const float*)d_in[24];
    const float* fc2_w   = (const float*)d_in[25];
    const float* fc2_b   = (const float*)d_in[26];
    const float* bn6_g   = (const float*)d_in[27];
    const float* bn6_b   = (const float*)d_in[28];
    float* out = (float*)d_out;

    float *p1, *p2, *p3, *p4, *p5, *fc1o, *fc2o;
    ull *pk1, *pk2, *pk3, *pk4, *pk5, *pk6, *w2, *w3, *w4, *w5, *wfc1, *wfc2;
    cudaGetSymbolAddress((void**)&p1,   g_p1);
    cudaGetSymbolAddress((void**)&p2,   g_p2);
    cudaGetSymbolAddress((void**)&p3,   g_p3);
    cudaGetSymbolAddress((void**)&p4,   g_p4);
    cudaGetSymbolAddress((void**)&p5,   g_p5);
    cudaGetSymbolAddress((void**)&fc1o, g_fc1o);
    cudaGetSymbolAddress((void**)&fc2o, g_fc2o);
    cudaGetSymbolAddress((void**)&pk1,  g_pk1);
    cudaGetSymbolAddress((void**)&pk2,  g_pk2);
    cudaGetSymbolAddress((void**)&pk3,  g_pk3);
    cudaGetSymbolAddress((void**)&pk4,  g_pk4);
    cudaGetSymbolAddress((void**)&pk5,  g_pk5);
    cudaGetSymbolAddress((void**)&pk6,  g_pk6);
    cudaGetSymbolAddress((void**)&w2,   g_w2);
    cudaGetSymbolAddress((void**)&w3,   g_w3);
    cudaGetSymbolAddress((void**)&w4,   g_w4);
    cudaGetSymbolAddress((void**)&w5,   g_w5);
    cudaGetSymbolAddress((void**)&wfc1, g_wfc1);
    cudaGetSymbolAddress((void**)&wfc2, g_wfc2);

    // weight prep
    k_codew1 <<<(64*123  + 255)/256, 256>>>(conv1_w);
    k_packw  <<<(41*64   + 255)/256, 256>>>(conv2_w, w2, 64);
    k_packw  <<<(41*64   + 255)/256, 256>>>(conv3_w, w3, 64);
    k_packw  <<<(41*64   + 255)/256, 256>>>(conv4_w, w4, 64);
    k_packw  <<<(41*32   + 255)/256, 256>>>(conv5_w, w5, 32);
    k_packw_fc<<<(1024*13 + 255)/256, 256>>>(fc1_w, wfc1, 1024, 13);
    k_packw_fc<<<(1000*16 + 255)/256, 256>>>(fc2_w, wfc2, 1000, 16);

    // bn0 + hardtanh (fp32 mimic) + exact split
    k_zero_stats<<<1, 64>>>(3);
    k_stats   <<<dim3(3, 32), 256>>>(x, 3, L0);
    k_finalize<<<1, 64>>>(bn0_g, bn0_b, 3, (double)N_BATCH*(double)L0);
    k_apply_h0<<<(N_BATCH*3*L0 + 255)/256, 256>>>(x, bn0_g, bn0_b);

    // conv1 (exact int-split) + bias + pool
    k_conv1<<<dim3(N_BATCH, (LP1 + 31)/32), 512>>>(conv1_b);

    // bn1 + sign-pack (fp32 mimic)
    k_zero_stats<<<1, 64>>>(64);
    k_stats   <<<dim3(64, 16), 256>>>(p1, 64, LP1);
    k_finalize<<<1, 64>>>(bn1_g, bn1_b, 64, (double)N_BATCH*(double)LP1);
    k_bnpack1 <<<(N_BATCH*LP1 + 255)/256, 256>>>(p1, pk1, LP1, bn1_g, bn1_b);

    // conv2
    k_binconv<64,4,4><<<dim3(N_BATCH, (LP2 + 15)/16), 256>>>(pk1, w2, conv2_b, p2, LP1, LP2);
    k_zero_stats<<<1, 64>>>(64);
    k_stats   <<<dim3(64, 16), 256>>>(p2, 64, LP2);
    k_finalize<<<1, 64>>>(bn2_g, bn2_b, 64, (double)N_BATCH*(double)LP2);
    k_bnpack  <<<(N_BATCH*LP2 + 255)/256, 256>>>(p2, pk2, LP2);

    // conv3
    k_binconv<64,4,4><<<dim3(N_BATCH, (LP3 + 15)/16), 256>>>(pk2, w3, conv3_b, p3, LP2, LP3);
    k_zero_stats<<<1, 64>>>(64);
    k_stats   <<<dim3(64, 16), 256>>>(p3, 64, LP3);
    k_finalize<<<1, 64>>>(bn3_g, bn3_b, 64, (double)N_BATCH*(double)LP3);
    k_bnpack  <<<(N_BATCH*LP3 + 255)/256, 256>>>(p3, pk3, LP3);

    // conv4
    k_binconv<64,4,4><<<dim3(N_BATCH, (LP4 + 15)/16), 256>>>(pk3, w4, conv4_b, p4, LP3, LP4);
    k_zero_stats<<<1, 64>>>(64);
    k_stats   <<<dim3(64, 16), 256>>>(p4, 64, LP4);
    k_finalize<<<1, 64>>>(bn4_g, bn4_b, 64, (double)N_BATCH*(double)LP4);
    k_bnpack  <<<(N_BATCH*LP4 + 255)/256, 256>>>(p4, pk4, LP4);

    // conv5 + fc path
    k_binconv<32,8,2><<<dim3(N_BATCH, (LP5 + 15)/16), 256>>>(pk4, w5, conv5_b, p5, LP4, LP5);
    k_packfc1in<<<(N_BATCH*13 + 255)/256, 256>>>();

    k_fc   <<<(N_BATCH*1024 + 255)/256, 256>>>(pk5, wfc1, fc1_b, fc1o, 1024, 13, 832);
    k_bnfc <<<(1024 + 255)/256, 256>>>(fc1o, bn5_g, bn5_b, 1024);
    k_pack6<<<(N_BATCH*16 + 255)/256, 256>>>();

    k_fc   <<<(N_BATCH*1000 + 255)/256, 256>>>(pk6, wfc2, fc2_b, fc2o, 1000, 16, 1024);
    k_bnfc <<<(1000 + 255)/256, 256>>>(fc2o, bn6_g, bn6_b, 1000);
    k_logsoftmax<<<N_BATCH, 256>>>(out);
}

// round 16
// speedup vs baseline: 1.4275x; 1.1344x over previous
#include <cuda_runtime.h>
#include <math.h>

typedef unsigned long long ull;
typedef signed char schar;   // 'char' is UNSIGNED on aarch64 — must be explicit

#define N_BATCH 64
#define L0 16000
#define LP1 5306
#define LP2 1742
#define LP3 554
#define LP4 158
#define LP5 26

// ---------------- scratch (device globals; no allocation allowed) ----------------
__device__ int   g_h0i[N_BATCH*3*L0];       // round(h * 2^20), exact int part
__device__ float g_h0r[N_BATCH*3*L0];       // h - i*2^-20, exact residual
__device__ float g_p1[N_BATCH*64*LP1];
__device__ ull   g_pk1[N_BATCH*LP1];
__device__ float g_p2[N_BATCH*64*LP2];
__device__ ull   g_pk2[N_BATCH*LP2];
__device__ float g_p3[N_BATCH*64*LP3];
__device__ ull   g_pk3[N_BATCH*LP3];
__device__ float g_p4[N_BATCH*64*LP4];
__device__ ull   g_pk4[N_BATCH*LP4];
__device__ float g_p5[N_BATCH*32*LP5];
__device__ ull   g_pk5[N_BATCH*13];
__device__ float g_fc1o[N_BATCH*1024];
__device__ ull   g_pk6[N_BATCH*16];
__device__ float g_fc2o[N_BATCH*1000];

__device__ schar g_w1code[123*64];          // conv1 weight sign codes, [(c*41+k)*64+o]
__device__ ull   g_w2[41*64];
__device__ ull   g_w3[41*64];
__device__ ull   g_w4[41*64];
__device__ ull   g_w5[41*32];
__device__ ull   g_wfc1[1024*13];
__device__ ull   g_wfc2[1000*16];

__device__ double g_ps[32*64], g_pq[32*64]; // per-(ygrid,channel) partial sums (deterministic)
__device__ float  g_a[1024], g_bb[1024];    // folded scale/shift (integer-grid layers + fc)
__device__ float  g_mf[64],  g_sf[64];      // fp32-mimic mean / sqrt(var+eps) (bn0, bn1)

// ---------------- weight prep ----------------
__global__ void k_codew1(const float* __restrict__ w){
    int idx = blockIdx.x*blockDim.x + threadIdx.x;   // idx = o*123 + (c*41+k)
    if (idx >= 64*123) return;
    int o = idx / 123, r = idx - o*123;
    float v = w[idx];
    schar code = (v > 0.f) ? (schar)1 : ((v < 0.f) ? (schar)-1 : (schar)0);
    g_w1code[r*64 + o] = code;
}

// conv weights (COUT,64,41): block per o, coalesced GMEM stage -> smem -> pack
__global__ void k_packw(const float* __restrict__ w, ull* __restrict__ wp, int COUT){
    __shared__ unsigned char s_b[64*41];
    int o = blockIdx.x;
    int t = threadIdx.x;                 // 128 threads
    for (int i = t; i < 64*41; i += 128)
        s_b[i] = (w[o*64*41 + i] > 0.f) ? 1 : 0;
    __syncthreads();
    if (t < 41){
        ull word = 0;
        #pragma unroll 8
        for (int c = 0; c < 64; c++)
            word |= (ull)s_b[c*41 + t] << c;
        wp[t*COUT + o] = word;
    }
}

// fc weights (F, W*64): one warp per packed word, coalesced + ballot
__global__ void k_packw_fc(const float* __restrict__ w, ull* __restrict__ wp, int F, int W){
    int gw = (blockIdx.x*blockDim.x + threadIdx.x) >> 5;
    int lane = threadIdx.x & 31;
    if (gw >= F*W) return;
    const float* base = w + (size_t)gw*64;   // f*INF + wd*64 == gw*64 (contiguous words)
    unsigned lo = __ballot_sync(0xFFFFFFFFu, base[lane]      > 0.f);
    unsigned hi = __ballot_sync(0xFFFFFFFFu, base[lane + 32] > 0.f);
    if (lane == 0) wp[gw] = ((ull)hi << 32) | lo;
}

// ---------------- batchnorm stats: deterministic per-block partials ----------------
__global__ void k_stats(const float* __restrict__ p, int C, int L){
    int c = blockIdx.x;
    int NL = N_BATCH * L;
    double s = 0.0, s2 = 0.0;
    for (int idx = blockIdx.y*blockDim.x + threadIdx.x; idx < NL; idx += gridDim.y*blockDim.x){
        int n = idx / L, l = idx - n*L;
        float v = p[(n*C + c)*L + l];
        s += (double)v; s2 += (double)v*(double)v;
    }
    __shared__ double sh[256], sh2[256];
    int t = threadIdx.x;
    sh[t] = s; sh2[t] = s2; __syncthreads();
    for (int st = 128; st > 0; st >>= 1){
        if (t < st){ sh[t] += sh[t+st]; sh2[t] += sh2[t+st]; }
        __syncthreads();
    }
    if (t == 0){ g_ps[blockIdx.y*64 + c] = sh[0]; g_pq[blockIdx.y*64 + c] = sh2[0]; }
}

__global__ void k_finalize(const float* __restrict__ g, const float* __restrict__ b,
                           int C, double cnt, int Y){
    int c = blockIdx.x*blockDim.x + threadIdx.x;
    if (c >= C) return;
    double s = 0.0, q = 0.0;
    for (int y = 0; y < Y; y++){ s += g_ps[y*64 + c]; q += g_pq[y*64 + c]; }
    double m = s/cnt;
    double v = q/cnt - m*m;
    double a = (double)g[c] / sqrt(v + 1e-5);
    g_a[c]  = (float)a;
    g_bb[c] = (float)((double)b[c] - m*a);
    float vf = (float)v;
    g_mf[c] = (float)m;
    g_sf[c] = __fsqrt_rn(__fadd_rn(vf, 1e-5f));
}

// ---------------- layer 0: bn0 + hardtanh (fp32 mimic) + exact int/residual split
__global__ void k_apply_h0(const float* __restrict__ x, const float* __restrict__ g,
                           const float* __restrict__ b){
    int idx = blockIdx.x*blockDim.x + threadIdx.x;
    if (idx >= N_BATCH*3*L0) return;
    int c = (idx / L0) % 3;
    float t1 = __fadd_rn(x[idx], -g_mf[c]);
    float t2 = __fdiv_rn(t1, g_sf[c]);
    float t3 = __fmul_rn(t2, g[c]);
    float t4 = __fadd_rn(t3, b[c]);
    float h  = fminf(1.f, fmaxf(-1.f, t4));
    float t  = __fmul_rn(h, 1048576.0f);          // h * 2^20, exact (pow2)
    int   i  = __float2int_rn(t);
    float fi = (float)i;                           // |i| <= 2^20 -> exact
    float r  = __fmaf_rn(fi, -0x1p-20f, h);        // exact residual
    g_h0i[idx] = i;
    g_h0r[idx] = r;
}

// ---------------- conv1: exact integer-split conv (3->64, K=41, dil=2) + bias + maxpool3
// 512 threads = 64 out-channels x 8 groups; each thread: 4 pooled (12 raw) outputs.
// residual path uses packed fma.rn.f32x2 (bit-identical to two scalar __fmaf_rn).
__global__ void __launch_bounds__(512) k_conv1(const float* __restrict__ bias){
    __shared__ int   s_ii[3][192];
    __shared__ float s_ir[3][192];
    __shared__ schar s_code[123*64];
    int n  = blockIdx.x;
    int pb = blockIdx.y * 32;                      // pooled base
    int rawbase = pb*3;
    int tid = threadIdx.x;
    int o = tid & 63, grp = tid >> 6;              // grp 0..7
    for (int i = tid; i < 3*192; i += 512){
        int c = i / 192, j = i - c*192;
        int src = rawbase + j; if (src > L0-1) src = L0-1;
        s_ii[c][j] = g_h0i[(n*3+c)*L0 + src];
        s_ir[c][j] = g_h0r[(n*3+c)*L0 + src];
    }
    for (int i = tid; i < 123*64; i += 512) s_code[i] = g_w1code[i];
    __syncthreads();

    ull ap[6]; int acci[12];
    #pragma unroll
    for (int j = 0; j < 6; j++) ap[j] = 0ull;
    #pragma unroll
    for (int r = 0; r < 12; r++) acci[r] = 0;
    int tb = grp*12;                               // even -> 8B-aligned pair loads

    #pragma unroll 1
    for (int c = 0; c < 3; c++){
        int iwin[12]; ull rpw[6];
        #pragma unroll
        for (int j = 0; j < 6; j++){
            int2 iv = *(const int2*)&s_ii[c][tb + 2*j];
            iwin[2*j] = iv.x; iwin[2*j+1] = iv.y;
            float2 fv = *(const float2*)&s_ir[c][tb + 2*j];
            asm("mov.b64 %0, {%1,%2};" : "=l"(rpw[j]) : "f"(fv.x), "f"(fv.y));
        }
        #pragma unroll
        for (int k = 0; k < 41; k++){
            int wi = (int)s_code[(c*41+k)*64 + o];     // -1 / 0 / +1
            float wf = (float)wi;
            ull wp2; asm("mov.b64 %0, {%1,%1};" : "=l"(wp2) : "f"(wf));
            int X  = wi >> 31;                          // -1 if neg else 0
            int A  = (wi | (-wi)) >> 31;                // -1 if nonzero else 0
            int cb = ((unsigned)wi) >> 31;              // +1 if neg else 0
            #pragma unroll
            for (int j = 0; j < 6; j++)
                asm("fma.rn.f32x2 %0, %1, %2, %0;" : "+l"(ap[j]) : "l"(wp2), "l"(rpw[j]));
            #pragma unroll
            for (int r = 0; r < 6; r++)                 // fma-pipe int MAC
                acci[r] += wi * iwin[r];
            #pragma unroll
            for (int r = 6; r < 12; r++)                // alu-pipe: LOP3 + IADD3
                acci[r] = acci[r] + ((iwin[r] & A) ^ X) + cb;
            if (k < 40){
                #pragma unroll
                for (int r = 0; r < 10; r++) iwin[r] = iwin[r+2];
                #pragma unroll
                for (int j = 0; j < 5; j++) rpw[j] = rpw[j+1];
                int2 iv = *(const int2*)&s_ii[c][tb + 2*k + 12];
                iwin[10] = iv.x; iwin[11] = iv.y;
                float2 fv = *(const float2*)&s_ir[c][tb + 2*k + 12];
                asm("mov.b64 %0, {%1,%2};" : "=l"(rpw[5]) : "f"(fv.x), "f"(fv.y));
            }
        }
    }

    float accr[12];
    #pragma unroll
    for (int j = 0; j < 6; j++)
        asm("mov.b64 {%0,%1}, %2;" : "=f"(accr[2*j]), "=f"(accr[2*j+1]) : "l"(ap[j]));

    const float S = 0x1p-20f;
    float b = bias[o];
    #pragma unroll
    for (int gq = 0; gq < 4; gq++){
        int p = pb + grp*4 + gq;
        if (p < LP1){
            float v[3];
            #pragma unroll
            for (int q = 0; q < 3; q++){
                int ai = acci[gq*3+q];
                int lo = ai & 4095;
                int hi2 = ai - lo;                      // multiple of 4096, exact in fp32
                float fint = __fadd_rn(__fmul_rn((float)hi2, S), __fmul_rn((float)lo, S));
                v[q] = __fadd_rn(fint, accr[gq*3+q]);
            }
            float m = fmaxf(v[0], fmaxf(v[1], v[2]));
            g_p1[(n*64+o)*LP1 + p] = __fadd_rn(m, b);
        }
    }
}

// ---------------- bn1 sign-pack: IEEE fp32 mimic of ((v-m)/s)*g+b > 0 -----------
__global__ void k_bnpack1(const float* __restrict__ p, ull* __restrict__ pk, int L,
                          const float* __restrict__ g, const float* __restrict__ b){
    int idx = blockIdx.x*blockDim.x + threadIdx.x;
    if (idx >= N_BATCH*L) return;
    int n = idx / L, l = idx - n*L;
    ull w = 0;
    #pragma unroll 8
    for (int c = 0; c < 64; c++){
        float t1 = __fadd_rn(p[(n*64+c)*L + l], -g_mf[c]);
        float t2 = __fdiv_rn(t1, g_sf[c]);
        float t3 = __fmul_rn(t2, g[c]);
        float t4 = __fadd_rn(t3, b[c]);
        if (t4 > 0.f) w |= (1ull << c);
    }
    pk[idx] = w;
}

// ---------------- sign-pack via folded BN (safe on integer-grid layers) ---------
__global__ void k_bnpack(const float* __restrict__ p, ull* __restrict__ pk, int L){
    int idx = blockIdx.x*blockDim.x + threadIdx.x;
    if (idx >= N_BATCH*L) return;
    int n = idx / L, l = idx - n*L;
    ull w = 0;
    #pragma unroll 8
    for (int c = 0; c < 64; c++){
        float v = p[(n*64+c)*L + l]*g_a[c] + g_bb[c];
        if (v > 0.f) w |= (1ull << c);
    }
    pk[idx] = w;
}

// ---------------- binarized conv (Cin=64) + bias + maxpool3 ---------------------
template<int COUT, int GRPS, int G>
__global__ void __launch_bounds__(COUT*GRPS)
k_binconv(const ull* __restrict__ in, const ull* __restrict__ wp,
          const float* __restrict__ bias, float* __restrict__ out,
          int Lin, int Lpool){
    const int PB = GRPS*G;
    const int TI = 3*PB + 80;
    __shared__ __align__(16) ull s_in[TI];
    __shared__ ull s_w[41*COUT];
    int n  = blockIdx.x;
    int pb = blockIdx.y*PB;
    int rawbase = 3*pb;
    int tid = threadIdx.x;
    int o = tid % COUT, grp = tid / COUT;
    for (int i = tid; i < TI; i += COUT*GRPS){
        int src = rawbase + i; if (src > Lin-1) src = Lin-1;
        s_in[i] = in[n*Lin + src];
    }
    for (int i = tid; i < 41*COUT; i += COUT*GRPS) s_w[i] = wp[i];
    __syncthreads();
    int acc[3*G];
    #pragma unroll
    for (int r = 0; r < 3*G; r++) acc[r] = 0;
    int tb = grp*3*G;
    #pragma unroll 1
    for (int k = 0; k < 41; k++){
        ull wv = s_w[k*COUT + o];
        const ulonglong2* ip = (const ulonglong2*)&s_in[tb + 2*k];
        #pragma unroll
        for (int r = 0; r < (3*G)/2; r++){
            ulonglong2 u = ip[r];
            acc[2*r]   += __popcll(u.x ^ wv);
            acc[2*r+1] += __popcll(u.y ^ wv);
        }
    }
    float b = bias[o];
    #pragma unroll
    for (int gq = 0; gq < G; gq++){
        int p = pb + grp*G + gq;
        if (p < Lpool){
            int v0 = 2624 - 2*acc[gq*3];
            int v1 = 2624 - 2*acc[gq*3+1];
            int v2 = 2624 - 2*acc[gq*3+2];
            int m = max(v0, max(v1, v2));
            out[(n*COUT+o)*Lpool + p] = __fadd_rn((float)m, b);
        }
    }
}

// ---------------- fc path ----------------
__global__ void k_packfc1in(){
    int idx = blockIdx.x*blockDim.x + threadIdx.x;
    if (idx >= N_BATCH*13) return;
    int n = idx / 13, wd = idx - n*13;
    ull word = 0;
    #pragma unroll 8
    for (int j = 0; j < 64; j++){
        float v = g_p5[n*832 + wd*64 + j];
        if (v > 0.f) word |= (1ull << j);
    }
    g_pk5[idx] = word;
}

__global__ void k_fc(const ull* __restrict__ inpk, const ull* __restrict__ wpk,
                     const float* __restrict__ bias, float* __restrict__ out,
                     int F, int W, int INB){
    int idx = blockIdx.x*blockDim.x + threadIdx.x;
    if (idx >= N_BATCH*F) return;
    int n = idx / F, f = idx - n*F;
    int acc = 0;
    for (int w = 0; w < W; w++) acc += __popcll(inpk[n*W+w] ^ wpk[f*W+w]);
    out[idx] = __fadd_rn((float)(INB - 2*acc), bias[f]);
}

__global__ void k_bnfc(const float* __restrict__ o, const float* __restrict__ g,
                       const float* __restrict__ b, int F){
    int f = blockIdx.x*blockDim.x + threadIdx.x;
    if (f >= F) return;
    double s = 0.0, s2 = 0.0;
    for (int n = 0; n < N_BATCH; n++){
        float v = o[n*F + f];
        s += (double)v; s2 += (double)v*(double)v;
    }
    double m = s / N_BATCH, var = s2 / N_BATCH - m*m;
    double a = (double)g[f] / sqrt(var + 1e-5);
    g_a[f]  = (float)a;
    g_bb[f] = (float)((double)b[f] - m*a);
}

__global__ void k_pack6(){
    int idx = blockIdx.x*blockDim.x + threadIdx.x;
    if (idx >= N_BATCH*16) return;
    int n = idx / 16, wd = idx - n*16;
    ull word = 0;
    #pragma unroll 8
    for (int j = 0; j < 64; j++){
        int f = wd*64 + j;
        float v = g_fc1o[n*1024+f]*g_a[f] + g_bb[f];
        if (v > 0.f) word |= (1ull << j);
    }
    g_pk6[idx] = word;
}

__global__ void k_logsoftmax(float* __restrict__ out){
    int n = blockIdx.x;
    int t = threadIdx.x;
    float yv[4];
    float mx = -1e30f;
    #pragma unroll
    for (int s = 0; s < 4; s++){
        int f = t + s*256;
        if (f < 1000){
            float y = g_fc2o[n*1000+f]*g_a[f] + g_bb[f];
            yv[s] = y; mx = fmaxf(mx, y);
        } else yv[s] = -1e30f;
    }
    __shared__ float sh[256];
    sh[t] = mx; __syncthreads();
    for (int st = 128; st > 0; st >>= 1){
        if (t < st) sh[t] = fmaxf(sh[t], sh[t+st]);
        __syncthreads();
    }
    mx = sh[0]; __syncthreads();
    float se = 0.f;
    #pragma unroll
    for (int s = 0; s < 4; s++){
        int f = t + s*256;
        if (f < 1000) se += expf(yv[s] - mx);
    }
    sh[t] = se; __syncthreads();
    for (int st = 128; st > 0; st >>= 1){
        if (t < st) sh[t] += sh[t+st];
        __syncthreads();
    }
    float lse = logf(sh[0]);
    #pragma unroll
    for (int s = 0; s < 4; s++){
        int f = t + s*256;
        if (f < 1000) out[n*1000+f] = yv[s] - mx - lse;
    }
}

// ---------------- launch ----------------
extern "C" void kernel_launch(void* const* d_in, const int* in_sizes, int n_in,
                              void* d_out, int out_size){
    const float* x       = (const float*)d_in[0];
    const float* bn0_g   = (const float*)d_in[1];
    const float* bn0_b   = (const float*)d_in[2];
    const float* conv1_w = (const float*)d_in[3];
    const float* conv1_b = (const float*)d_in[4];
    const float* bn1_g   = (const float*)d_in[5];
    const float* bn1_b   = (const float*)d_in[6];
    const float* conv2_w = (const float*)d_in[7];
    const float* conv2_b = (const float*)d_in[8];
    const float* bn2_g   = (const float*)d_in[9];
    const float* bn2_b   = (const float*)d_in[10];
    const float* conv3_w = (const float*)d_in[11];
    const float* conv3_b = (const float*)d_in[12];
    const float* bn3_g   = (const float*)d_in[13];
    const float* bn3_b   = (const float*)d_in[14];
    const float* conv4_w = (const float*)d_in[15];
    const float* conv4_b = (const float*)d_in[16];
    const float* bn4_g   = (const float*)d_in[17];
    const float* bn4_b   = (const float*)d_in[18];
    const float* conv5_w = (const float*)d_in[19];
    const float* conv5_b = (const float*)d_in[20];
    const float* fc1_w   = (const float*)d_in[21];
    const float* fc1_b   = (const float*)d_in[22];
    const float* bn5_g   = (const float*)d_in[23];
    const float* bn5_b   = (const float*)d_in[24];
    const float* fc2_w   = (const float*)d_in[25];
    const float* fc2_b   = (const float*)d_in[26];
    const float* bn6_g   = (const float*)d_in[27];
    const float* bn6_b   = (const float*)d_in[28];
    float* out = (float*)d_out;

    float *p1, *p2, *p3, *p4, *p5, *fc1o, *fc2o;
    ull *pk1, *pk2, *pk3, *pk4, *pk5, *pk6, *w2, *w3, *w4, *w5, *wfc1, *wfc2;
    cudaGetSymbolAddress((void**)&p1,   g_p1);
    cudaGetSymbolAddress((void**)&p2,   g_p2);
    cudaGetSymbolAddress((void**)&p3,   g_p3);
    cudaGetSymbolAddress((void**)&p4,   g_p4);
    cudaGetSymbolAddress((void**)&p5,   g_p5);
    cudaGetSymbolAddress((void**)&fc1o, g_fc1o);
    cudaGetSymbolAddress((void**)&fc2o, g_fc2o);
    cudaGetSymbolAddress((void**)&pk1,  g_pk1);
    cudaGetSymbolAddress((void**)&pk2,  g_pk2);
    cudaGetSymbolAddress((void**)&pk3,  g_pk3);
    cudaGetSymbolAddress((void**)&pk4,  g_pk4);
    cudaGetSymbolAddress((void**)&pk5,  g_pk5);
    cudaGetSymbolAddress((void**)&pk6,  g_pk6);
    cudaGetSymbolAddress((void**)&w2,   g_w2);
    cudaGetSymbolAddress((void**)&w3,   g_w3);
    cudaGetSymbolAddress((void**)&w4,   g_w4);
    cudaGetSymbolAddress((void**)&w5,   g_w5);
    cudaGetSymbolAddress((void**)&wfc1, g_wfc1);
    cudaGetSymbolAddress((void**)&wfc2, g_wfc2);

    // ---- launches 1-6: conv1 is #6 so ncu (-s 5 -c 1) profiles it ----
    k_codew1 <<<(64*123 + 255)/256, 256>>>(conv1_w);                    // 1
    k_stats   <<<dim3(3, 32), 256>>>(x, 3, L0);                         // 2 (bn0)
    k_finalize<<<1, 64>>>(bn0_g, bn0_b, 3, (double)N_BATCH*(double)L0, 32); // 3
    k_apply_h0<<<(N_BATCH*3*L0 + 255)/256, 256>>>(x, bn0_g, bn0_b);     // 4
    k_packw   <<<64, 128>>>(conv2_w, w2, 64);                           // 5
    k_conv1   <<<dim3(N_BATCH, (LP1 + 31)/32), 512>>>(conv1_b);         // 6  <-- profiled

    // remaining weight prep (before their consumers)
    k_packw   <<<64, 128>>>(conv3_w, w3, 64);
    k_packw   <<<64, 128>>>(conv4_w, w4, 64);
    k_packw   <<<32, 128>>>(conv5_w, w5, 32);
    k_packw_fc<<<(1024*13*32 + 255)/256, 256>>>(fc1_w, wfc1, 1024, 13);
    k_packw_fc<<<(1000*16*32 + 255)/256, 256>>>(fc2_w, wfc2, 1000, 16);

    // bn1 + sign-pack (fp32 mimic)
    k_stats   <<<dim3(64, 16), 256>>>(p1, 64, LP1);
    k_finalize<<<1, 64>>>(bn1_g, bn1_b, 64, (double)N_BATCH*(double)LP1, 16);
    k_bnpack1 <<<(N_BATCH*LP1 + 255)/256, 256>>>(p1, pk1, LP1, bn1_g, bn1_b);

    // conv2
    k_binconv<64,4,4><<<dim3(N_BATCH, (LP2 + 15)/16), 256>>>(pk1, w2, conv2_b, p2, LP1, LP2);
    k_stats   <<<dim3(64, 16), 256>>>(p2, 64, LP2);
    k_finalize<<<1, 64>>>(bn2_g, bn2_b, 64, (double)N_BATCH*(double)LP2, 16);
    k_bnpack  <<<(N_BATCH*LP2 + 255)/256, 256>>>(p2, pk2, LP2);

    // conv3
    k_binconv<64,4,4><<<dim3(N_BATCH, (LP3 + 15)/16), 256>>>(pk2, w3, conv3_b, p3, LP2, LP3);
    k_stats   <<<dim3(64, 16), 256>>>(p3, 64, LP3);
    k_finalize<<<1, 64>>>(bn3_g, bn3_b, 64, (double)N_BATCH*(double)LP3, 16);
    k_bnpack  <<<(N_BATCH*LP3 + 255)/256, 256>>>(p3, pk3, LP3);

    // conv4
    k_binconv<64,4,4><<<dim3(N_BATCH, (LP4 + 15)/16), 256>>>(pk3, w4, conv4_b, p4, LP3, LP4);
    k_stats   <<<dim3(64, 16), 256>>>(p4, 64, LP4);
    k_finalize<<<1, 64>>>(bn4_g, bn4_b, 64, (double)N_BATCH*(double)LP4, 16);
    k_bnpack  <<<(N_BATCH*LP4 + 255)/256, 256>>>(p4, pk4, LP4);

    // conv5 + fc path
    k_binconv<32,8,2><<<dim3(N_BATCH, (LP5 + 15)/16), 256>>>(pk4, w5, conv5_b, p5, LP4, LP5);
    k_packfc1in<<<(N_BATCH*13 + 255)/256, 256>>>();

    k_fc   <<<(N_BATCH*1024 + 255)/256, 256>>>(pk5, wfc1, fc1_b, fc1o, 1024, 13, 832);
    k_bnfc <<<(1024 + 255)/256, 256>>>(fc1o, bn5_g, bn5_b, 1024);
    k_pack6<<<(N_BATCH*16 + 255)/256, 256>>>();

    k_fc   <<<(N_BATCH*1000 + 255)/256, 256>>>(pk6, wfc2, fc2_b, fc2o, 1000, 16, 1024);
    k_bnfc <<<(1000 + 255)/256, 256>>>(fc2o, bn6_g, bn6_b, 1000);
    k_logsoftmax<<<N_BATCH, 256>>>(out);
}